// round 2
// baseline (speedup 1.0000x reference)
#include <cuda_runtime.h>
#include <math.h>

#define SEQ 1024
#define HID 4096
#define NH  64
#define HD  64

// Scratch (allocation-free rule: __device__ globals)
__device__ float g_kb[SEQ * HID];
__device__ float g_vb[SEQ * HID];
__device__ float g_rb[SEQ * HID];
__device__ float g_gb[SEQ * HID];
__device__ float g_ab[SEQ * HID];

#define BM 128
#define BN 128
#define BK 8

// ---------------------------------------------------------------------------
// Projection GEMM: out[m,n] = sum_k mix(hidden)[m,k] * W[n,k]
// mix fused into A-tile load; SiLU fused into gate epilogue.
// blockIdx.z selects projection {key, value, receptance, gate}.
// ---------------------------------------------------------------------------
__global__ __launch_bounds__(256) void proj_kernel(
    const float* __restrict__ hidden,
    const float* __restrict__ wk, const float* __restrict__ wv,
    const float* __restrict__ wr, const float* __restrict__ wg,
    const float* __restrict__ mk, const float* __restrict__ mv,
    const float* __restrict__ mr, const float* __restrict__ mg)
{
    const float* W;
    const float* mixv;
    float* out;
    bool do_silu = false;
    switch (blockIdx.z) {
        case 0:  W = wk; mixv = mk; out = g_kb; break;
        case 1:  W = wv; mixv = mv; out = g_vb; break;
        case 2:  W = wr; mixv = mr; out = g_rb; break;
        default: W = wg; mixv = mg; out = g_gb; do_silu = true; break;
    }

    __shared__ float As[BK][BM];
    __shared__ float Bs[BK][BN];

    const int tid = threadIdx.x;
    const int tx = tid & 15;
    const int ty = tid >> 4;
    const int m0 = blockIdx.y * BM;
    const int n0 = blockIdx.x * BN;
    const int lrow = tid >> 1;          // 0..127
    const int lcol = (tid & 1) * 4;     // 0 or 4

    float acc[8][8];
    #pragma unroll
    for (int i = 0; i < 8; i++)
        #pragma unroll
        for (int j = 0; j < 8; j++)
            acc[i][j] = 0.f;

    const int m = m0 + lrow;
    const float* hrow = hidden + (size_t)m * HID;
    const float* srow = hidden + (size_t)(m - 1) * HID;   // only read if m>0
    const float* wrow = W + (size_t)(n0 + lrow) * HID;

    for (int k0 = 0; k0 < HID; k0 += BK) {
        float4 hv = *(const float4*)(hrow + k0 + lcol);
        float4 sv = make_float4(0.f, 0.f, 0.f, 0.f);
        if (m > 0) sv = *(const float4*)(srow + k0 + lcol);
        float4 mvx = *(const float4*)(mixv + k0 + lcol);
        As[lcol + 0][lrow] = hv.x * mvx.x + sv.x * (1.f - mvx.x);
        As[lcol + 1][lrow] = hv.y * mvx.y + sv.y * (1.f - mvx.y);
        As[lcol + 2][lrow] = hv.z * mvx.z + sv.z * (1.f - mvx.z);
        As[lcol + 3][lrow] = hv.w * mvx.w + sv.w * (1.f - mvx.w);

        float4 bv = *(const float4*)(wrow + k0 + lcol);
        Bs[lcol + 0][lrow] = bv.x;
        Bs[lcol + 1][lrow] = bv.y;
        Bs[lcol + 2][lrow] = bv.z;
        Bs[lcol + 3][lrow] = bv.w;
        __syncthreads();

        #pragma unroll
        for (int kk = 0; kk < BK; kk++) {
            float4 a0 = *(const float4*)&As[kk][ty * 8];
            float4 a1 = *(const float4*)&As[kk][ty * 8 + 4];
            float4 b0 = *(const float4*)&Bs[kk][tx * 8];
            float4 b1 = *(const float4*)&Bs[kk][tx * 8 + 4];
            float a[8] = {a0.x, a0.y, a0.z, a0.w, a1.x, a1.y, a1.z, a1.w};
            float b[8] = {b0.x, b0.y, b0.z, b0.w, b1.x, b1.y, b1.z, b1.w};
            #pragma unroll
            for (int i = 0; i < 8; i++)
                #pragma unroll
                for (int j = 0; j < 8; j++)
                    acc[i][j] = fmaf(a[i], b[j], acc[i][j]);
        }
        __syncthreads();
    }

    #pragma unroll
    for (int i = 0; i < 8; i++) {
        int mi = m0 + ty * 8 + i;
        #pragma unroll
        for (int j = 0; j < 8; j += 4) {
            float4 v = make_float4(acc[i][j], acc[i][j + 1], acc[i][j + 2], acc[i][j + 3]);
            if (do_silu) {
                v.x = v.x / (1.f + expf(-v.x));
                v.y = v.y / (1.f + expf(-v.y));
                v.z = v.z / (1.f + expf(-v.z));
                v.w = v.w / (1.f + expf(-v.w));
            }
            *(float4*)(out + (size_t)mi * HID + n0 + tx * 8 + j) = v;
        }
    }
}

// ---------------------------------------------------------------------------
// WKV recurrence + fused GroupNorm + gate.
// One CTA per head. 256 threads: e = tid&63 (value column), dg = tid>>6
// (16 key-rows of state per thread).
//   o_e   = sum_d r_d * (tf_d * k_d * v_e + state[d][e])
//   state = k_d * v_e + td_d * state
// Then per (t,h): GroupNorm over the 64 o's, scale/shift, multiply by gate.
// ---------------------------------------------------------------------------
__global__ __launch_bounds__(256) void wkv_kernel(
    const float* __restrict__ time_decay, const float* __restrict__ time_faaaa,
    const float* __restrict__ gn_w, const float* __restrict__ gn_b)
{
    const int h = blockIdx.x;
    const int tid = threadIdx.x;
    const int e = tid & 63;
    const int dg = tid >> 6;       // 0..3
    const int dbase = dg * 16;

    __shared__ float ks[64], rs[64], vs[64], gs[64];
    __shared__ float opart[4][64];
    __shared__ float red[4];

    float td[16], tf[16], st[16];
    #pragma unroll
    for (int j = 0; j < 16; j++) {
        int d = dbase + j;
        td[j] = expf(-expf(time_decay[h * HD + d]));
        tf[j] = time_faaaa[h * HD + d];
        st[j] = 0.f;
    }
    const float gw = gn_w[h * HD + e];
    const float gb = gn_b[h * HD + e];

    const float* kb = g_kb + h * HD;
    const float* rb = g_rb + h * HD;
    const float* vb = g_vb + h * HD;
    const float* gp = g_gb + h * HD;

    for (int t = 0; t < SEQ; t++) {
        const int base = t * HID;
        if (tid < 64)        ks[tid]       = kb[base + tid];
        else if (tid < 128)  rs[tid - 64]  = rb[base + tid - 64];
        else if (tid < 192)  vs[tid - 128] = vb[base + tid - 128];
        else                 gs[tid - 192] = gp[base + tid - 192];
        __syncthreads();

        const float gval = gs[e];   // capture before shared reuse hazard
        const float ve = vs[e];
        float o0 = 0.f, o1 = 0.f;
        #pragma unroll
        for (int j = 0; j < 16; j += 2) {
            float kv0 = ks[dbase + j] * ve;
            o0 = fmaf(rs[dbase + j], fmaf(tf[j], kv0, st[j]), o0);
            st[j] = fmaf(td[j], st[j], kv0);
            float kv1 = ks[dbase + j + 1] * ve;
            o1 = fmaf(rs[dbase + j + 1], fmaf(tf[j + 1], kv1, st[j + 1]), o1);
            st[j + 1] = fmaf(td[j + 1], st[j + 1], kv1);
        }
        opart[dg][e] = o0 + o1;
        __syncthreads();

        float o = 0.f;
        if (tid < 64) {
            o = opart[0][e] + opart[1][e] + opart[2][e] + opart[3][e];
            float s = o, s2 = o * o;
            #pragma unroll
            for (int off = 16; off > 0; off >>= 1) {
                s  += __shfl_xor_sync(0xffffffffu, s,  off);
                s2 += __shfl_xor_sync(0xffffffffu, s2, off);
            }
            if ((tid & 31) == 0) {
                red[(tid >> 5) * 2]     = s;
                red[(tid >> 5) * 2 + 1] = s2;
            }
        }
        __syncthreads();

        if (tid < 64) {
            float mean = (red[0] + red[2]) * (1.f / 64.f);
            float m2   = (red[1] + red[3]) * (1.f / 64.f);
            float var = m2 - mean * mean;
            float xn = (o - mean) * rsqrtf(var + 1e-5f) * gw + gb;
            g_ab[base + h * HD + e] = xn * gval;
        }
        // No extra barrier needed: next-iter shared writes are ordered by
        // the 3 barriers above (gval captured early).
    }
}

// ---------------------------------------------------------------------------
// Output GEMM: out[m,n] = sum_k g_ab[m,k] * Wout[n,k]
// ---------------------------------------------------------------------------
__global__ __launch_bounds__(256) void out_kernel(
    const float* __restrict__ W, float* __restrict__ outp)
{
    __shared__ float As[BK][BM];
    __shared__ float Bs[BK][BN];

    const int tid = threadIdx.x;
    const int tx = tid & 15;
    const int ty = tid >> 4;
    const int m0 = blockIdx.y * BM;
    const int n0 = blockIdx.x * BN;
    const int lrow = tid >> 1;
    const int lcol = (tid & 1) * 4;

    float acc[8][8];
    #pragma unroll
    for (int i = 0; i < 8; i++)
        #pragma unroll
        for (int j = 0; j < 8; j++)
            acc[i][j] = 0.f;

    const float* arow = g_ab + (size_t)(m0 + lrow) * HID;
    const float* wrow = W + (size_t)(n0 + lrow) * HID;

    for (int k0 = 0; k0 < HID; k0 += BK) {
        float4 av = *(const float4*)(arow + k0 + lcol);
        As[lcol + 0][lrow] = av.x;
        As[lcol + 1][lrow] = av.y;
        As[lcol + 2][lrow] = av.z;
        As[lcol + 3][lrow] = av.w;
        float4 bv = *(const float4*)(wrow + k0 + lcol);
        Bs[lcol + 0][lrow] = bv.x;
        Bs[lcol + 1][lrow] = bv.y;
        Bs[lcol + 2][lrow] = bv.z;
        Bs[lcol + 3][lrow] = bv.w;
        __syncthreads();

        #pragma unroll
        for (int kk = 0; kk < BK; kk++) {
            float4 a0 = *(const float4*)&As[kk][ty * 8];
            float4 a1 = *(const float4*)&As[kk][ty * 8 + 4];
            float4 b0 = *(const float4*)&Bs[kk][tx * 8];
            float4 b1 = *(const float4*)&Bs[kk][tx * 8 + 4];
            float a[8] = {a0.x, a0.y, a0.z, a0.w, a1.x, a1.y, a1.z, a1.w};
            float b[8] = {b0.x, b0.y, b0.z, b0.w, b1.x, b1.y, b1.z, b1.w};
            #pragma unroll
            for (int i = 0; i < 8; i++)
                #pragma unroll
                for (int j = 0; j < 8; j++)
                    acc[i][j] = fmaf(a[i], b[j], acc[i][j]);
        }
        __syncthreads();
    }

    #pragma unroll
    for (int i = 0; i < 8; i++) {
        int mi = m0 + ty * 8 + i;
        #pragma unroll
        for (int j = 0; j < 8; j += 4) {
            float4 v = make_float4(acc[i][j], acc[i][j + 1], acc[i][j + 2], acc[i][j + 3]);
            *(float4*)(outp + (size_t)mi * HID + n0 + tx * 8 + j) = v;
        }
    }
}

// ---------------------------------------------------------------------------
extern "C" void kernel_launch(void* const* d_in, const int* in_sizes, int n_in,
                              void* d_out, int out_size)
{
    const float* hidden     = (const float*)d_in[0];
    const float* w_key      = (const float*)d_in[1];
    const float* w_value    = (const float*)d_in[2];
    const float* w_recept   = (const float*)d_in[3];
    const float* w_gate     = (const float*)d_in[4];
    const float* w_output   = (const float*)d_in[5];
    const float* tm_key     = (const float*)d_in[6];
    const float* tm_value   = (const float*)d_in[7];
    const float* tm_recept  = (const float*)d_in[8];
    const float* tm_gate    = (const float*)d_in[9];
    const float* time_decay = (const float*)d_in[10];
    const float* time_faaaa = (const float*)d_in[11];
    const float* gn_w       = (const float*)d_in[12];
    const float* gn_b       = (const float*)d_in[13];

    dim3 gproj(HID / BN, SEQ / BM, 4);
    proj_kernel<<<gproj, 256>>>(hidden, w_key, w_value, w_recept, w_gate,
                                tm_key, tm_value, tm_recept, tm_gate);

    wkv_kernel<<<NH, 256>>>(time_decay, time_faaaa, gn_w, gn_b);

    dim3 gout(HID / BN, SEQ / BM, 1);
    out_kernel<<<gout, 256>>>(w_output, (float*)d_out);
}

// round 5
// speedup vs baseline: 3.7345x; 3.7345x over previous
#include <cuda_runtime.h>
#include <cuda_bf16.h>
#include <math.h>
#include <stdint.h>

#define SEQ 1024
#define HID 4096
#define NH  64
#define HD  64
#define SZ  (SEQ*HID)

__device__ float          g_kvrg[4*SZ];     // k,v,r,g(silu) fp32
__device__ float          g_opart[8*SZ];    // WKV partials per d-group
__device__ __nv_bfloat16  g_mAh[4*SZ];      // mixed activations hi
__device__ __nv_bfloat16  g_mAl[4*SZ];      // mixed activations lo
__device__ __nv_bfloat16  g_abh[SZ];        // normed/gated hi
__device__ __nv_bfloat16  g_abl[SZ];        // normed/gated lo

__device__ __forceinline__ uint32_t pk(__nv_bfloat16 a, __nv_bfloat16 b){
    __nv_bfloat162 t = __halves2bfloat162(a, b);
    return *reinterpret_cast<uint32_t*>(&t);
}
__device__ __forceinline__ void split_bf(float x, __nv_bfloat16& h, __nv_bfloat16& l){
    h = __float2bfloat16(x);
    l = __float2bfloat16(x - __bfloat162float(h));
}
__device__ __forceinline__ float silu(float x){ return x / (1.f + expf(-x)); }

__device__ __forceinline__ void mma16816(float* c, const uint32_t* a, uint32_t b0, uint32_t b1){
    asm volatile("mma.sync.aligned.m16n8k16.row.col.f32.bf16.bf16.f32 "
        "{%0,%1,%2,%3}, {%4,%5,%6,%7}, {%8,%9}, {%0,%1,%2,%3};"
        : "+f"(c[0]), "+f"(c[1]), "+f"(c[2]), "+f"(c[3])
        : "r"(a[0]), "r"(a[1]), "r"(a[2]), "r"(a[3]), "r"(b0), "r"(b1));
}

// ---------------- prepass: token-shift mix -> split bf16 --------------------
__global__ __launch_bounds__(256) void prepass_kernel(
    const float* __restrict__ hidden, const float* __restrict__ mk,
    const float* __restrict__ mv, const float* __restrict__ mr, const float* __restrict__ mg)
{
    int idx = (blockIdx.x*256 + threadIdx.x)*4;
    int t = idx >> 12, c = idx & 4095;
    float4 hv = *(const float4*)(hidden + idx);
    float4 sv = make_float4(0.f,0.f,0.f,0.f);
    if (t > 0) sv = *(const float4*)(hidden + idx - HID);
    const float* ms[4] = {mk, mv, mr, mg};
    #pragma unroll
    for (int p = 0; p < 4; p++){
        float4 m = *(const float4*)(ms[p] + c);
        float x0 = hv.x*m.x + sv.x*(1.f-m.x), x1 = hv.y*m.y + sv.y*(1.f-m.y);
        float x2 = hv.z*m.z + sv.z*(1.f-m.z), x3 = hv.w*m.w + sv.w*(1.f-m.w);
        __nv_bfloat16 h0,h1,h2,h3,l0,l1,l2,l3;
        split_bf(x0,h0,l0); split_bf(x1,h1,l1); split_bf(x2,h2,l2); split_bf(x3,h3,l3);
        *(uint2*)(g_mAh + (size_t)p*SZ + idx) = make_uint2(pk(h0,h1), pk(h2,h3));
        *(uint2*)(g_mAl + (size_t)p*SZ + idx) = make_uint2(pk(l0,l1), pk(l2,l3));
    }
}

// ---------------- mma.sync GEMM: C[M,N]=A[M,K]*W[N,K]^T ---------------------
// Tile 128x128, K-chunk 64. 8 warps (4m x 2n), warp tile 32x64.
// Split-bf16: C = Ah*Bh + Ah*Bl + Al*Bh  (Al*Bl term ~2^-16, dropped)
#define KC 64
#define SP 72                      // padded bf16 row stride
#define ATILE (128*SP)
#define GSMEM (4*ATILE*2)          // Ah | Al | Bh | Bl  (bytes)

__global__ __launch_bounds__(256, 2) void gemm_kernel(
    int mode, const float* __restrict__ W0, const float* __restrict__ W1,
    const float* __restrict__ W2, const float* __restrict__ W3, float* __restrict__ dout)
{
    extern __shared__ __nv_bfloat16 sm[];
    __nv_bfloat16* Ah = sm;
    __nv_bfloat16* Al = sm + ATILE;
    __nv_bfloat16* Bh = sm + 2*ATILE;
    __nv_bfloat16* Bl = sm + 3*ATILE;

    const int tid = threadIdx.x, z = blockIdx.z;
    const __nv_bfloat16 *AhG, *AlG;
    const float* W;
    float* outp;
    bool do_silu = false;
    if (mode == 0){
        AhG = g_mAh + (size_t)z*SZ; AlG = g_mAl + (size_t)z*SZ;
        W = (z==0)?W0:(z==1)?W1:(z==2)?W2:W3;
        outp = g_kvrg + (size_t)z*SZ; do_silu = (z==3);
    } else { AhG = g_abh; AlG = g_abl; W = W0; outp = dout; }

    const int m0 = blockIdx.y*128, n0 = blockIdx.x*128;
    const int wid = tid>>5, lane = tid&31;
    const int wm = (wid&3)*32, wn = (wid>>2)*64;
    const int r = lane>>2, q = lane&3;

    float acc[2][8][4];
    #pragma unroll
    for (int i=0;i<2;i++)
        #pragma unroll
        for (int j=0;j<8;j++)
            #pragma unroll
            for (int k=0;k<4;k++) acc[i][j][k]=0.f;

    for (int c = 0; c < HID/KC; c++){
        const int k0 = c*KC;
        __syncthreads();
        #pragma unroll
        for (int i = 0; i < 4; i++){                 // A hi/lo: 128 rows x 64 bf16
            int u = tid + 256*i, row = u>>3, seg = u&7;   // 8 segs x 8 bf16 (uint4)
            size_t g = (size_t)(m0+row)*HID + k0 + seg*8;
            *(uint4*)(Ah + row*SP + seg*8) = *(const uint4*)(AhG + g);
            *(uint4*)(Al + row*SP + seg*8) = *(const uint4*)(AlG + g);
        }
        #pragma unroll
        for (int i = 0; i < 8; i++){                 // B: 128 rows x 64 fp32 -> split
            int u = tid + 256*i, row = u>>4, seg = u&15;
            float4 w4 = *(const float4*)(W + (size_t)(n0+row)*HID + k0 + seg*4);
            __nv_bfloat16 h0,h1,h2,h3,l0,l1,l2,l3;
            split_bf(w4.x,h0,l0); split_bf(w4.y,h1,l1); split_bf(w4.z,h2,l2); split_bf(w4.w,h3,l3);
            *(uint2*)(Bh + row*SP + seg*4) = make_uint2(pk(h0,h1), pk(h2,h3));
            *(uint2*)(Bl + row*SP + seg*4) = make_uint2(pk(l0,l1), pk(l2,l3));
        }
        __syncthreads();

        #pragma unroll
        for (int ko = 0; ko < KC; ko += 16){
            uint32_t ah[2][4], al[2][4];
            #pragma unroll
            for (int fm = 0; fm < 2; fm++){
                int ra = wm + fm*16 + r;
                ah[fm][0] = *(const uint32_t*)(Ah + ra*SP     + ko + q*2);
                ah[fm][1] = *(const uint32_t*)(Ah + (ra+8)*SP + ko + q*2);
                ah[fm][2] = *(const uint32_t*)(Ah + ra*SP     + ko + 8 + q*2);
                ah[fm][3] = *(const uint32_t*)(Ah + (ra+8)*SP + ko + 8 + q*2);
                al[fm][0] = *(const uint32_t*)(Al + ra*SP     + ko + q*2);
                al[fm][1] = *(const uint32_t*)(Al + (ra+8)*SP + ko + q*2);
                al[fm][2] = *(const uint32_t*)(Al + ra*SP     + ko + 8 + q*2);
                al[fm][3] = *(const uint32_t*)(Al + (ra+8)*SP + ko + 8 + q*2);
            }
            #pragma unroll
            for (int fn = 0; fn < 8; fn++){
                int rb = wn + fn*8 + r;
                uint32_t bh0 = *(const uint32_t*)(Bh + rb*SP + ko + q*2);
                uint32_t bh1 = *(const uint32_t*)(Bh + rb*SP + ko + 8 + q*2);
                uint32_t bl0 = *(const uint32_t*)(Bl + rb*SP + ko + q*2);
                uint32_t bl1 = *(const uint32_t*)(Bl + rb*SP + ko + 8 + q*2);
                #pragma unroll
                for (int fm = 0; fm < 2; fm++){
                    mma16816(acc[fm][fn], ah[fm], bh0, bh1);
                    mma16816(acc[fm][fn], ah[fm], bl0, bl1);
                    mma16816(acc[fm][fn], al[fm], bh0, bh1);
                }
            }
        }
    }

    #pragma unroll
    for (int fm = 0; fm < 2; fm++){
        #pragma unroll
        for (int fn = 0; fn < 8; fn++){
            int row0 = m0 + wm + fm*16 + r;
            int col  = n0 + wn + fn*8 + q*2;
            float2 v0 = make_float2(acc[fm][fn][0], acc[fm][fn][1]);
            float2 v1 = make_float2(acc[fm][fn][2], acc[fm][fn][3]);
            if (do_silu){
                v0.x = silu(v0.x); v0.y = silu(v0.y);
                v1.x = silu(v1.x); v1.y = silu(v1.y);
            }
            *(float2*)(outp + (size_t)row0*HID + col)     = v0;
            *(float2*)(outp + (size_t)(row0+8)*HID + col) = v1;
        }
    }
}

// ---------------- WKV recurrence, barrier-light -----------------------------
__global__ __launch_bounds__(256) void wkv_kernel(
    const float* __restrict__ time_decay, const float* __restrict__ time_faaaa)
{
    const int head = blockIdx.x, ehalf = blockIdx.y;
    const int tid = threadIdx.x, eg = tid & 31, dg = tid >> 5;
    __shared__ float ks[16][64], rs[16][64], vs[16][32];

    float td[8], tf[8], stv[8];
    #pragma unroll
    for (int j = 0; j < 8; j++){
        int d = dg*8 + j;
        td[j] = expf(-expf(time_decay[head*HD + d]));
        tf[j] = time_faaaa[head*HD + d];
        stv[j] = 0.f;
    }
    const float* kb = g_kvrg + 0*(size_t)SZ + head*HD;
    const float* vb = g_kvrg + 1*(size_t)SZ + head*HD + ehalf*32;
    const float* rb = g_kvrg + 2*(size_t)SZ + head*HD;
    float* op = g_opart + (size_t)dg*SZ + head*HD + ehalf*32;

    const int ktrow = tid >> 4, kseg = tid & 15;
    const int vtrow = tid >> 3, vseg = tid & 7;
    float4 ka, ra, va;
    ka = *(const float4*)(kb + (size_t)ktrow*HID + kseg*4);
    ra = *(const float4*)(rb + (size_t)ktrow*HID + kseg*4);
    if (tid < 128) va = *(const float4*)(vb + (size_t)vtrow*HID + vseg*4);

    for (int c = 0; c < SEQ/16; c++){
        __syncthreads();
        *(float4*)&ks[ktrow][kseg*4] = ka;
        *(float4*)&rs[ktrow][kseg*4] = ra;
        if (tid < 128) *(float4*)&vs[vtrow][vseg*4] = va;
        __syncthreads();
        if (c < SEQ/16 - 1){
            const size_t t1 = (size_t)(c+1)*16;
            ka = *(const float4*)(kb + (t1+ktrow)*HID + kseg*4);
            ra = *(const float4*)(rb + (t1+ktrow)*HID + kseg*4);
            if (tid < 128) va = *(const float4*)(vb + (t1+vtrow)*HID + vseg*4);
        }
        #pragma unroll
        for (int tt = 0; tt < 16; tt++){
            const float ve = vs[tt][eg];
            float4 k0 = *(const float4*)&ks[tt][dg*8];
            float4 k1 = *(const float4*)&ks[tt][dg*8+4];
            float4 r0 = *(const float4*)&rs[tt][dg*8];
            float4 r1 = *(const float4*)&rs[tt][dg*8+4];
            float kv, o = 0.f;
            kv = k0.x*ve; o = fmaf(r0.x, fmaf(tf[0],kv,stv[0]), o); stv[0] = fmaf(td[0],stv[0],kv);
            kv = k0.y*ve; o = fmaf(r0.y, fmaf(tf[1],kv,stv[1]), o); stv[1] = fmaf(td[1],stv[1],kv);
            kv = k0.z*ve; o = fmaf(r0.z, fmaf(tf[2],kv,stv[2]), o); stv[2] = fmaf(td[2],stv[2],kv);
            kv = k0.w*ve; o = fmaf(r0.w, fmaf(tf[3],kv,stv[3]), o); stv[3] = fmaf(td[3],stv[3],kv);
            kv = k1.x*ve; o = fmaf(r1.x, fmaf(tf[4],kv,stv[4]), o); stv[4] = fmaf(td[4],stv[4],kv);
            kv = k1.y*ve; o = fmaf(r1.y, fmaf(tf[5],kv,stv[5]), o); stv[5] = fmaf(td[5],stv[5],kv);
            kv = k1.z*ve; o = fmaf(r1.z, fmaf(tf[6],kv,stv[6]), o); stv[6] = fmaf(td[6],stv[6],kv);
            kv = k1.w*ve; o = fmaf(r1.w, fmaf(tf[7],kv,stv[7]), o); stv[7] = fmaf(td[7],stv[7],kv);
            op[(size_t)(c*16+tt)*HID + eg] = o;
        }
    }
}

// ---------------- GroupNorm + gate + split-bf16 -----------------------------
__global__ __launch_bounds__(256) void norm_kernel(
    const float* __restrict__ gnw, const float* __restrict__ gnb)
{
    const int wid = threadIdx.x >> 5, lane = threadIdx.x & 31;
    const int g = blockIdx.x*8 + wid;
    const int t = g >> 6, h = g & 63, e0 = lane*2;
    const size_t bse = (size_t)t*HID + h*HD + e0;

    float o0 = 0.f, o1 = 0.f;
    #pragma unroll
    for (int dg = 0; dg < 8; dg++){
        float2 v = *(const float2*)(g_opart + (size_t)dg*SZ + bse);
        o0 += v.x; o1 += v.y;
    }
    float s = o0 + o1, s2 = o0*o0 + o1*o1;
    #pragma unroll
    for (int off = 16; off > 0; off >>= 1){
        s  += __shfl_xor_sync(0xffffffffu, s,  off);
        s2 += __shfl_xor_sync(0xffffffffu, s2, off);
    }
    const float mean = s * (1.f/64.f);
    const float var  = s2 * (1.f/64.f) - mean*mean;
    const float rstd = rsqrtf(var + 1e-5f);
    float2 gt = *(const float2*)(g_kvrg + 3*(size_t)SZ + bse);
    const float w0 = gnw[h*HD+e0], w1 = gnw[h*HD+e0+1];
    const float b0 = gnb[h*HD+e0], b1 = gnb[h*HD+e0+1];
    float y0 = ((o0-mean)*rstd*w0 + b0) * gt.x;
    float y1 = ((o1-mean)*rstd*w1 + b1) * gt.y;
    __nv_bfloat16 h0,h1,l0,l1;
    split_bf(y0,h0,l0); split_bf(y1,h1,l1);
    *(uint32_t*)(g_abh + bse) = pk(h0,h1);
    *(uint32_t*)(g_abl + bse) = pk(l0,l1);
}

// ---------------------------------------------------------------------------
extern "C" void kernel_launch(void* const* d_in, const int* in_sizes, int n_in,
                              void* d_out, int out_size)
{
    const float* hidden     = (const float*)d_in[0];
    const float* w_key      = (const float*)d_in[1];
    const float* w_value    = (const float*)d_in[2];
    const float* w_recept   = (const float*)d_in[3];
    const float* w_gate     = (const float*)d_in[4];
    const float* w_output   = (const float*)d_in[5];
    const float* tm_key     = (const float*)d_in[6];
    const float* tm_value   = (const float*)d_in[7];
    const float* tm_recept  = (const float*)d_in[8];
    const float* tm_gate    = (const float*)d_in[9];
    const float* time_decay = (const float*)d_in[10];
    const float* time_faaaa = (const float*)d_in[11];
    const float* gn_w       = (const float*)d_in[12];
    const float* gn_b       = (const float*)d_in[13];

    cudaFuncSetAttribute(gemm_kernel, cudaFuncAttributeMaxDynamicSharedMemorySize, GSMEM);

    prepass_kernel<<<SZ/1024, 256>>>(hidden, tm_key, tm_value, tm_recept, tm_gate);

    dim3 gproj(HID/128, SEQ/128, 4);
    gemm_kernel<<<gproj, 256, GSMEM>>>(0, w_key, w_value, w_recept, w_gate, nullptr);

    dim3 gwkv(NH, 2);
    wkv_kernel<<<gwkv, 256>>>(time_decay, time_faaaa);

    norm_kernel<<<SEQ*NH/8, 256>>>(gn_w, gn_b);

    dim3 gout(HID/128, SEQ/128, 1);
    gemm_kernel<<<gout, 256, GSMEM>>>(1, w_output, nullptr, nullptr, nullptr, (float*)d_out);
}

// round 6
// speedup vs baseline: 5.7468x; 1.5389x over previous
#include <cuda_runtime.h>
#include <cuda_bf16.h>
#include <math.h>
#include <stdint.h>

#define SEQ 1024
#define HID 4096
#define NH  64
#define HD  64
#define SZ  (SEQ*HID)
#define SZW (HID*HID)

__device__ float          g_kvrg[4*SZ];     // k,v,r,g(silu) fp32
__device__ float          g_opart[8*SZ];    // WKV partials per d-group
__device__ __nv_bfloat16  g_mAh[4*SZ];      // mixed activations hi
__device__ __nv_bfloat16  g_mAl[4*SZ];      // mixed activations lo
__device__ __nv_bfloat16  g_abh[SZ];        // normed/gated hi
__device__ __nv_bfloat16  g_abl[SZ];        // normed/gated lo
__device__ __nv_bfloat16  g_Wh[5*SZW];      // weights hi (k,v,r,g,o)
__device__ __nv_bfloat16  g_Wl[5*SZW];      // weights lo

__device__ __forceinline__ uint32_t pk(__nv_bfloat16 a, __nv_bfloat16 b){
    __nv_bfloat162 t = __halves2bfloat162(a, b);
    return *reinterpret_cast<uint32_t*>(&t);
}
__device__ __forceinline__ void split_bf(float x, __nv_bfloat16& h, __nv_bfloat16& l){
    h = __float2bfloat16(x);
    l = __float2bfloat16(x - __bfloat162float(h));
}
__device__ __forceinline__ float silu(float x){ return x / (1.f + expf(-x)); }
__device__ __forceinline__ uint32_t smem_u32(const void* p){
    uint32_t a;
    asm("{ .reg .u64 t; cvta.to.shared.u64 t, %1; cvt.u32.u64 %0, t; }" : "=r"(a) : "l"(p));
    return a;
}
__device__ __forceinline__ void mma16816(float* c, const uint32_t* a, uint32_t b0, uint32_t b1){
    asm volatile("mma.sync.aligned.m16n8k16.row.col.f32.bf16.bf16.f32 "
        "{%0,%1,%2,%3}, {%4,%5,%6,%7}, {%8,%9}, {%0,%1,%2,%3};"
        : "+f"(c[0]), "+f"(c[1]), "+f"(c[2]), "+f"(c[3])
        : "r"(a[0]), "r"(a[1]), "r"(a[2]), "r"(a[3]), "r"(b0), "r"(b1));
}
__device__ __forceinline__ void ldsm4(uint32_t* r, uint32_t a){
    asm volatile("ldmatrix.sync.aligned.m8n8.x4.shared.b16 {%0,%1,%2,%3}, [%4];"
        : "=r"(r[0]), "=r"(r[1]), "=r"(r[2]), "=r"(r[3]) : "r"(a));
}
__device__ __forceinline__ void ldsm2(uint32_t* r, uint32_t a){
    asm volatile("ldmatrix.sync.aligned.m8n8.x2.shared.b16 {%0,%1}, [%2];"
        : "=r"(r[0]), "=r"(r[1]) : "r"(a));
}
__device__ __forceinline__ void cpa16(uint32_t dst, const void* src){
    asm volatile("cp.async.cg.shared.global [%0], [%1], 16;" :: "r"(dst), "l"(src));
}
#define CPA_COMMIT() asm volatile("cp.async.commit_group;" ::: "memory")
#define CPA_WAIT1()  asm volatile("cp.async.wait_group 1;" ::: "memory")

// ---------------- weight prepass: fp32 -> split bf16 ------------------------
__global__ __launch_bounds__(256) void prepass_w_kernel(
    const float* __restrict__ wk, const float* __restrict__ wv,
    const float* __restrict__ wr, const float* __restrict__ wg,
    const float* __restrict__ wo)
{
    const int p = blockIdx.y;
    const float* W = (p==0)?wk:(p==1)?wv:(p==2)?wr:(p==3)?wg:wo;
    size_t idx = ((size_t)blockIdx.x*256 + threadIdx.x)*4;
    float4 w4 = *(const float4*)(W + idx);
    __nv_bfloat16 h0,h1,h2,h3,l0,l1,l2,l3;
    split_bf(w4.x,h0,l0); split_bf(w4.y,h1,l1); split_bf(w4.z,h2,l2); split_bf(w4.w,h3,l3);
    *(uint2*)(g_Wh + (size_t)p*SZW + idx) = make_uint2(pk(h0,h1), pk(h2,h3));
    *(uint2*)(g_Wl + (size_t)p*SZW + idx) = make_uint2(pk(l0,l1), pk(l2,l3));
}

// ---------------- activation prepass: mix -> split bf16 ---------------------
__global__ __launch_bounds__(256) void prepass_kernel(
    const float* __restrict__ hidden, const float* __restrict__ mk,
    const float* __restrict__ mv, const float* __restrict__ mr, const float* __restrict__ mg)
{
    int idx = (blockIdx.x*256 + threadIdx.x)*4;
    int t = idx >> 12, c = idx & 4095;
    float4 hv = *(const float4*)(hidden + idx);
    float4 sv = make_float4(0.f,0.f,0.f,0.f);
    if (t > 0) sv = *(const float4*)(hidden + idx - HID);
    const float* ms[4] = {mk, mv, mr, mg};
    #pragma unroll
    for (int p = 0; p < 4; p++){
        float4 m = *(const float4*)(ms[p] + c);
        float x0 = hv.x*m.x + sv.x*(1.f-m.x), x1 = hv.y*m.y + sv.y*(1.f-m.y);
        float x2 = hv.z*m.z + sv.z*(1.f-m.z), x3 = hv.w*m.w + sv.w*(1.f-m.w);
        __nv_bfloat16 h0,h1,h2,h3,l0,l1,l2,l3;
        split_bf(x0,h0,l0); split_bf(x1,h1,l1); split_bf(x2,h2,l2); split_bf(x3,h3,l3);
        *(uint2*)(g_mAh + (size_t)p*SZ + idx) = make_uint2(pk(h0,h1), pk(h2,h3));
        *(uint2*)(g_mAl + (size_t)p*SZ + idx) = make_uint2(pk(l0,l1), pk(l2,l3));
    }
}

// ---------------- mma.sync GEMM, 3-stage cp.async pipeline ------------------
// C[M,N] = A[M,K] * W[N,K]^T.  Tile 128x128, KC=64, 8 warps (4m x 2n).
// Split-bf16: C = Ah*Bh + Ah*Bl + Al*Bh
#define KC 64
#define SP 72
#define TH (128*SP)              // elems per tile-half
#define NSTAGE 3
#define GSMEM (NSTAGE*4*TH*2)    // bytes

__global__ __launch_bounds__(256) void gemm_kernel(int mode, float* __restrict__ dout)
{
    extern __shared__ __nv_bfloat16 sm[];
    const int tid = threadIdx.x, z = blockIdx.z;
    const __nv_bfloat16 *AhG, *AlG, *BhG, *BlG;
    float* outp;
    bool do_silu = false;
    if (mode == 0){
        AhG = g_mAh + (size_t)z*SZ; AlG = g_mAl + (size_t)z*SZ;
        BhG = g_Wh + (size_t)z*SZW; BlG = g_Wl + (size_t)z*SZW;
        outp = g_kvrg + (size_t)z*SZ; do_silu = (z==3);
    } else {
        AhG = g_abh; AlG = g_abl;
        BhG = g_Wh + 4*(size_t)SZW; BlG = g_Wl + 4*(size_t)SZW;
        outp = dout;
    }

    const int m0 = blockIdx.x*128, n0 = blockIdx.y*128;
    const int wid = tid>>5, lane = tid&31;
    const int wm = (wid&3)*32, wn = (wid>>2)*64;
    const int r = lane>>2, q = lane&3;
    const uint32_t sbase = smem_u32(sm);

    const int crow = tid>>3, cseg = tid&7;          // copy: 32 rows x 8 segs / 256 thr
    const size_t gAoff = (size_t)(m0+crow)*HID + cseg*8;
    const size_t gBoff = (size_t)(n0+crow)*HID + cseg*8;
    const uint32_t soff = (uint32_t)(crow*SP + cseg*8)*2;

    float acc[2][8][4];
    #pragma unroll
    for (int i=0;i<2;i++)
        #pragma unroll
        for (int j=0;j<8;j++)
            #pragma unroll
            for (int k=0;k<4;k++) acc[i][j][k]=0.f;

    // issue copies for chunk c into stage s
    auto issue = [&](int c, int s){
        const int k0 = c*KC;
        const uint32_t st = sbase + (uint32_t)(s*4*TH)*2;
        #pragma unroll
        for (int i = 0; i < 4; i++){
            const uint32_t dof = soff + (uint32_t)(i*32*SP)*2;
            const size_t ga = gAoff + k0 + (size_t)i*32*HID;
            const size_t gb = gBoff + k0 + (size_t)i*32*HID;
            cpa16(st + dof,             AhG + ga);
            cpa16(st + (uint32_t)TH*2   + dof, AlG + ga);
            cpa16(st + (uint32_t)2*TH*2 + dof, BhG + gb);
            cpa16(st + (uint32_t)3*TH*2 + dof, BlG + gb);
        }
    };

    issue(0, 0); CPA_COMMIT();
    issue(1, 1); CPA_COMMIT();

    const int NCH = HID/KC;
    for (int c = 0; c < NCH; c++){
        const int s = c % NSTAGE;
        CPA_WAIT1();
        __syncthreads();
        if (c + 2 < NCH) issue(c + 2, (c + 2) % NSTAGE);
        CPA_COMMIT();

        const uint32_t stA_h = sbase + (uint32_t)(s*4*TH)*2;
        const uint32_t stA_l = stA_h + (uint32_t)TH*2;
        const uint32_t stB_h = stA_h + (uint32_t)2*TH*2;
        const uint32_t stB_l = stA_h + (uint32_t)3*TH*2;

        #pragma unroll
        for (int ko = 0; ko < KC; ko += 16){
            uint32_t ah[2][4], al[2][4], bh[8][2], bl[8][2];
            const int arow = wm + (lane&15), acol = ko + (lane>>4)*8;
            #pragma unroll
            for (int fm = 0; fm < 2; fm++){
                const uint32_t ao = (uint32_t)((arow + fm*16)*SP + acol)*2;
                ldsm4(ah[fm], stA_h + ao);
                ldsm4(al[fm], stA_l + ao);
            }
            const int brow = wn + (lane&7), bcol = ko + ((lane>>3)&1)*8;
            #pragma unroll
            for (int fn = 0; fn < 8; fn++){
                const uint32_t bo = (uint32_t)((brow + fn*8)*SP + bcol)*2;
                ldsm2(bh[fn], stB_h + bo);
                ldsm2(bl[fn], stB_l + bo);
            }
            #pragma unroll
            for (int fn = 0; fn < 8; fn++)
                #pragma unroll
                for (int fm = 0; fm < 2; fm++){
                    mma16816(acc[fm][fn], ah[fm], bh[fn][0], bh[fn][1]);
                    mma16816(acc[fm][fn], ah[fm], bl[fn][0], bl[fn][1]);
                    mma16816(acc[fm][fn], al[fm], bh[fn][0], bh[fn][1]);
                }
        }
        __syncthreads();
    }

    #pragma unroll
    for (int fm = 0; fm < 2; fm++){
        #pragma unroll
        for (int fn = 0; fn < 8; fn++){
            int row0 = m0 + wm + fm*16 + r;
            int col  = n0 + wn + fn*8 + q*2;
            float2 v0 = make_float2(acc[fm][fn][0], acc[fm][fn][1]);
            float2 v1 = make_float2(acc[fm][fn][2], acc[fm][fn][3]);
            if (do_silu){
                v0.x = silu(v0.x); v0.y = silu(v0.y);
                v1.x = silu(v1.x); v1.y = silu(v1.y);
            }
            *(float2*)(outp + (size_t)row0*HID + col)     = v0;
            *(float2*)(outp + (size_t)(row0+8)*HID + col) = v1;
        }
    }
}

// ---------------- WKV recurrence, barrier-light -----------------------------
__global__ __launch_bounds__(256) void wkv_kernel(
    const float* __restrict__ time_decay, const float* __restrict__ time_faaaa)
{
    const int head = blockIdx.x, ehalf = blockIdx.y;
    const int tid = threadIdx.x, eg = tid & 31, dg = tid >> 5;
    __shared__ float ks[16][64], rs[16][64], vs[16][32];

    float td[8], tf[8], stv[8];
    #pragma unroll
    for (int j = 0; j < 8; j++){
        int d = dg*8 + j;
        td[j] = expf(-expf(time_decay[head*HD + d]));
        tf[j] = time_faaaa[head*HD + d];
        stv[j] = 0.f;
    }
    const float* kb = g_kvrg + 0*(size_t)SZ + head*HD;
    const float* vb = g_kvrg + 1*(size_t)SZ + head*HD + ehalf*32;
    const float* rb = g_kvrg + 2*(size_t)SZ + head*HD;
    float* op = g_opart + (size_t)dg*SZ + head*HD + ehalf*32;

    const int ktrow = tid >> 4, kseg = tid & 15;
    const int vtrow = tid >> 3, vseg = tid & 7;
    float4 ka, ra, va;
    ka = *(const float4*)(kb + (size_t)ktrow*HID + kseg*4);
    ra = *(const float4*)(rb + (size_t)ktrow*HID + kseg*4);
    if (tid < 128) va = *(const float4*)(vb + (size_t)vtrow*HID + vseg*4);

    for (int c = 0; c < SEQ/16; c++){
        __syncthreads();
        *(float4*)&ks[ktrow][kseg*4] = ka;
        *(float4*)&rs[ktrow][kseg*4] = ra;
        if (tid < 128) *(float4*)&vs[vtrow][vseg*4] = va;
        __syncthreads();
        if (c < SEQ/16 - 1){
            const size_t t1 = (size_t)(c+1)*16;
            ka = *(const float4*)(kb + (t1+ktrow)*HID + kseg*4);
            ra = *(const float4*)(rb + (t1+ktrow)*HID + kseg*4);
            if (tid < 128) va = *(const float4*)(vb + (t1+vtrow)*HID + vseg*4);
        }
        #pragma unroll
        for (int tt = 0; tt < 16; tt++){
            const float ve = vs[tt][eg];
            float4 k0 = *(const float4*)&ks[tt][dg*8];
            float4 k1 = *(const float4*)&ks[tt][dg*8+4];
            float4 r0 = *(const float4*)&rs[tt][dg*8];
            float4 r1 = *(const float4*)&rs[tt][dg*8+4];
            float kv, o = 0.f;
            kv = k0.x*ve; o = fmaf(r0.x, fmaf(tf[0],kv,stv[0]), o); stv[0] = fmaf(td[0],stv[0],kv);
            kv = k0.y*ve; o = fmaf(r0.y, fmaf(tf[1],kv,stv[1]), o); stv[1] = fmaf(td[1],stv[1],kv);
            kv = k0.z*ve; o = fmaf(r0.z, fmaf(tf[2],kv,stv[2]), o); stv[2] = fmaf(td[2],stv[2],kv);
            kv = k0.w*ve; o = fmaf(r0.w, fmaf(tf[3],kv,stv[3]), o); stv[3] = fmaf(td[3],stv[3],kv);
            kv = k1.x*ve; o = fmaf(r1.x, fmaf(tf[4],kv,stv[4]), o); stv[4] = fmaf(td[4],stv[4],kv);
            kv = k1.y*ve; o = fmaf(r1.y, fmaf(tf[5],kv,stv[5]), o); stv[5] = fmaf(td[5],stv[5],kv);
            kv = k1.z*ve; o = fmaf(r1.z, fmaf(tf[6],kv,stv[6]), o); stv[6] = fmaf(td[6],stv[6],kv);
            kv = k1.w*ve; o = fmaf(r1.w, fmaf(tf[7],kv,stv[7]), o); stv[7] = fmaf(td[7],stv[7],kv);
            op[(size_t)(c*16+tt)*HID + eg] = o;
        }
    }
}

// ---------------- GroupNorm + gate + split-bf16 -----------------------------
__global__ __launch_bounds__(256) void norm_kernel(
    const float* __restrict__ gnw, const float* __restrict__ gnb)
{
    const int wid = threadIdx.x >> 5, lane = threadIdx.x & 31;
    const int g = blockIdx.x*8 + wid;
    const int t = g >> 6, h = g & 63, e0 = lane*2;
    const size_t bse = (size_t)t*HID + h*HD + e0;

    float o0 = 0.f, o1 = 0.f;
    #pragma unroll
    for (int dg = 0; dg < 8; dg++){
        float2 v = *(const float2*)(g_opart + (size_t)dg*SZ + bse);
        o0 += v.x; o1 += v.y;
    }
    float s = o0 + o1, s2 = o0*o0 + o1*o1;
    #pragma unroll
    for (int off = 16; off > 0; off >>= 1){
        s  += __shfl_xor_sync(0xffffffffu, s,  off);
        s2 += __shfl_xor_sync(0xffffffffu, s2, off);
    }
    const float mean = s * (1.f/64.f);
    const float var  = s2 * (1.f/64.f) - mean*mean;
    const float rstd = rsqrtf(var + 1e-5f);
    float2 gt = *(const float2*)(g_kvrg + 3*(size_t)SZ + bse);
    const float w0 = gnw[h*HD+e0], w1 = gnw[h*HD+e0+1];
    const float b0 = gnb[h*HD+e0], b1 = gnb[h*HD+e0+1];
    float y0 = ((o0-mean)*rstd*w0 + b0) * gt.x;
    float y1 = ((o1-mean)*rstd*w1 + b1) * gt.y;
    __nv_bfloat16 h0,h1,l0,l1;
    split_bf(y0,h0,l0); split_bf(y1,h1,l1);
    *(uint32_t*)(g_abh + bse) = pk(h0,h1);
    *(uint32_t*)(g_abl + bse) = pk(l0,l1);
}

// ---------------------------------------------------------------------------
extern "C" void kernel_launch(void* const* d_in, const int* in_sizes, int n_in,
                              void* d_out, int out_size)
{
    const float* hidden     = (const float*)d_in[0];
    const float* w_key      = (const float*)d_in[1];
    const float* w_value    = (const float*)d_in[2];
    const float* w_recept   = (const float*)d_in[3];
    const float* w_gate     = (const float*)d_in[4];
    const float* w_output   = (const float*)d_in[5];
    const float* tm_key     = (const float*)d_in[6];
    const float* tm_value   = (const float*)d_in[7];
    const float* tm_recept  = (const float*)d_in[8];
    const float* tm_gate    = (const float*)d_in[9];
    const float* time_decay = (const float*)d_in[10];
    const float* time_faaaa = (const float*)d_in[11];
    const float* gn_w       = (const float*)d_in[12];
    const float* gn_b       = (const float*)d_in[13];

    cudaFuncSetAttribute(gemm_kernel, cudaFuncAttributeMaxDynamicSharedMemorySize, GSMEM);

    dim3 gw(SZW/1024, 5);
    prepass_w_kernel<<<gw, 256>>>(w_key, w_value, w_recept, w_gate, w_output);
    prepass_kernel<<<SZ/1024, 256>>>(hidden, tm_key, tm_value, tm_recept, tm_gate);

    dim3 gproj(SEQ/128, HID/128, 4);
    gemm_kernel<<<gproj, 256, GSMEM>>>(0, nullptr);

    dim3 gwkv(NH, 2);
    wkv_kernel<<<gwkv, 256>>>(time_decay, time_faaaa);

    norm_kernel<<<SEQ*NH/8, 256>>>(gn_w, gn_b);

    dim3 gout(SEQ/128, HID/128, 1);
    gemm_kernel<<<gout, 256, GSMEM>>>(1, (float*)d_out);
}